// round 1
// baseline (speedup 1.0000x reference)
#include <cuda_runtime.h>
#include <cuda_bf16.h>

#define BDIM   8
#define CDIM   1024
#define HWDIM  32
#define NHEAD  16
#define HD     64

// ---------------- scratch (static device globals; no allocations) ----------
__device__ float g_Qc[BDIM * CDIM * CDIM];   // conv(q) as [b][c][p], p = h*32+w
__device__ float g_Kc[BDIM * CDIM * CDIM];
__device__ float g_Vc[BDIM * CDIM * CDIM];
__device__ float g_AO[BDIM * CDIM * CDIM];   // attention out [b][c][p], p = head*64+j

// ============================================================================
// Conv 3x3 SAME, implicit GEMM.
// Block: 64 out-channels x (8 rows x 32 cols) spatial patch. 256 threads.
// Thread (og,pg): og = tid/32 (8 o-values, o = o0+og*8+i), pg = tid%32 (w col),
// computes 8 o x 8 local rows. BK = 8 input channels per smem stage.
// ============================================================================
__global__ __launch_bounds__(256)
void conv3x3_kernel(const float* __restrict__ xq, const float* __restrict__ xk,
                    const float* __restrict__ xv,
                    const float* __restrict__ Wq, const float* __restrict__ Wk,
                    const float* __restrict__ Wv,
                    const float* __restrict__ bq, const float* __restrict__ bk,
                    const float* __restrict__ bv)
{
    const int which = blockIdx.z >> 3;   // 0=q 1=k 2=v
    const int b     = blockIdx.z & 7;

    const float* x;  const float* W;  const float* bias;  float* out;
    if (which == 0)      { x = xq; W = Wq; bias = bq; out = g_Qc; }
    else if (which == 1) { x = xk; W = Wk; bias = bk; out = g_Kc; }
    else                 { x = xv; W = Wv; bias = bv; out = g_Vc; }

    const int o0 = blockIdx.x * 64;
    const int h0 = blockIdx.y * 8;

    __shared__ float sX[8][10][34];   // [ic][row(-1..8)][col(-1..32)]
    __shared__ float sW[8][9][65];    // [ic][tap][o] padded to 65 (conflict-free stores)

    const int t  = threadIdx.x;
    const int og = t >> 5;    // 0..7
    const int pg = t & 31;    // 0..31  (w column)

    float acc[8][8];
    #pragma unroll
    for (int i = 0; i < 8; i++)
        #pragma unroll
        for (int j = 0; j < 8; j++) acc[i][j] = 0.f;

    const float* xb = x + (size_t)b * CDIM * HWDIM * HWDIM;

    for (int kc = 0; kc < CDIM; kc += 8) {
        // ---- stage input tile with halo (zeros at image border) ----
        for (int idx = t; idx < 8 * 10 * 34; idx += 256) {
            int ic  = idx / 340;
            int rem = idx % 340;
            int r   = rem / 34;        // 0..9 -> gh = h0 + r - 1
            int cc  = rem % 34;        // 0..33 -> gw = cc - 1
            int gh  = h0 + r - 1;
            int gw  = cc - 1;
            float val = 0.f;
            if (gh >= 0 && gh < HWDIM && gw >= 0 && gw < HWDIM)
                val = xb[(size_t)(kc + ic) * (HWDIM * HWDIM) + gh * HWDIM + gw];
            sX[ic][r][cc] = val;
        }
        // ---- stage weights: coalesced over (ic,tap), padded smem stores ----
        for (int idx = t; idx < 64 * 72; idx += 256) {
            int o   = idx / 72;
            int r   = idx % 72;        // r = ic*9 + tap  (contiguous in gmem)
            int ic  = r / 9;
            int tap = r % 9;
            sW[ic][tap][o] = W[(size_t)(o0 + o) * (CDIM * 9) + (size_t)kc * 9 + r];
        }
        __syncthreads();

        #pragma unroll
        for (int ic = 0; ic < 8; ic++) {
            #pragma unroll
            for (int kh = 0; kh < 3; kh++) {
                #pragma unroll
                for (int kw = 0; kw < 3; kw++) {
                    float wv[8], xvv[8];
                    #pragma unroll
                    for (int i = 0; i < 8; i++) wv[i] = sW[ic][kh * 3 + kw][og * 8 + i];
                    #pragma unroll
                    for (int j = 0; j < 8; j++) xvv[j] = sX[ic][j + kh][pg + kw];
                    #pragma unroll
                    for (int i = 0; i < 8; i++)
                        #pragma unroll
                        for (int j = 0; j < 8; j++)
                            acc[i][j] = fmaf(wv[i], xvv[j], acc[i][j]);
                }
            }
        }
        __syncthreads();
    }

    float* ob = out + (size_t)b * CDIM * CDIM;
    #pragma unroll
    for (int i = 0; i < 8; i++) {
        int o = o0 + og * 8 + i;
        float bv = bias[o];
        #pragma unroll
        for (int j = 0; j < 8; j++) {
            int p = (h0 + j) * HWDIM + pg;
            ob[(size_t)o * CDIM + p] = acc[i][j] + bv;
        }
    }
}

// ============================================================================
// Flash-style attention over channels-as-tokens.
//   qh[b,head,t,j] = Qc[b][t][head*64+j]  (t = channel token, j = head dim)
//   scores masked by mask[b][t][s], softmax over s, out = P @ V.
// Block: 64 query tokens x one (b,head). 256 threads (ty=tid/16, tx=tid%16),
// 4x4 register tiles for both S and O.
// ============================================================================
__global__ __launch_bounds__(256)
void attn_kernel(const int* __restrict__ mask)
{
    extern __shared__ float smem[];
    float* sQ = smem;               // 64*65
    float* sK = sQ + 64 * 65;       // 64*65
    float* sV = sK + 64 * 65;       // 64*65
    float* sS = sV + 64 * 65;       // 64*65
    float* sM = sS + 64 * 65;       // 64
    float* sL = sM + 64;            // 64
    float* sF = sL + 64;            // 64

    const int bh   = blockIdx.y;
    const int b    = bh >> 4;
    const int head = bh & 15;
    const int t0   = blockIdx.x * 64;

    const int t  = threadIdx.x;
    const int ty = t >> 4;          // 0..15
    const int tx = t & 15;          // 0..15

    const float* Qb = g_Qc + (size_t)b * CDIM * CDIM;
    const float* Kb = g_Kc + (size_t)b * CDIM * CDIM;
    const float* Vb = g_Vc + (size_t)b * CDIM * CDIM;
    const int    hb = head * HD;

    // stage Q tile [64 tokens][64 headdim]
    for (int idx = t; idx < 64 * 64; idx += 256) {
        int r = idx >> 6, k = idx & 63;
        sQ[r * 65 + k] = Qb[(size_t)(t0 + r) * CDIM + hb + k];
    }
    if (t < 64) { sM[t] = -1e30f; sL[t] = 0.f; }

    float acc[4][4];
    #pragma unroll
    for (int i = 0; i < 4; i++)
        #pragma unroll
        for (int j = 0; j < 4; j++) acc[i][j] = 0.f;

    const float scale = 0.125f;     // 1/sqrt(64)

    for (int sb = 0; sb < 16; sb++) {
        const int s0 = sb * 64;
        __syncthreads();   // protect sK/sV/sS reuse (and initial sQ/sM/sL)
        for (int idx = t; idx < 64 * 64; idx += 256) {
            int r = idx >> 6, k = idx & 63;
            sK[r * 65 + k] = Kb[(size_t)(s0 + r) * CDIM + hb + k];
            sV[r * 65 + k] = Vb[(size_t)(s0 + r) * CDIM + hb + k];
        }
        __syncthreads();

        // S = Q K^T  (4x4 per thread)
        float sv[4][4];
        #pragma unroll
        for (int i = 0; i < 4; i++)
            #pragma unroll
            for (int j = 0; j < 4; j++) sv[i][j] = 0.f;
        for (int k = 0; k < 64; k++) {
            float aq[4], bk_[4];
            #pragma unroll
            for (int i = 0; i < 4; i++) aq[i]  = sQ[(ty * 4 + i) * 65 + k];
            #pragma unroll
            for (int j = 0; j < 4; j++) bk_[j] = sK[(tx * 4 + j) * 65 + k];
            #pragma unroll
            for (int i = 0; i < 4; i++)
                #pragma unroll
                for (int j = 0; j < 4; j++)
                    sv[i][j] = fmaf(aq[i], bk_[j], sv[i][j]);
        }
        // scale + mask, park in sS
        #pragma unroll
        for (int i = 0; i < 4; i++) {
            int tg = t0 + ty * 4 + i;
            #pragma unroll
            for (int j = 0; j < 4; j++) {
                int sg = s0 + tx * 4 + j;
                float val = sv[i][j] * scale;
                int mv = mask[(size_t)b * CDIM * CDIM + (size_t)tg * CDIM + sg];
                if (mv == 0) val = -1e9f;
                sS[(ty * 4 + i) * 65 + tx * 4 + j] = val;
            }
        }
        __syncthreads();

        // online softmax row pass (one thread per row)
        if (t < 64) {
            float m_old = sM[t];
            float mx = m_old;
            for (int s = 0; s < 64; s++) mx = fmaxf(mx, sS[t * 65 + s]);
            float f = __expf(m_old - mx);
            float sum = 0.f;
            for (int s = 0; s < 64; s++) {
                float e = __expf(sS[t * 65 + s] - mx);
                sS[t * 65 + s] = e;
                sum += e;
            }
            sL[t] = sL[t] * f + sum;
            sM[t] = mx;
            sF[t] = f;
        }
        __syncthreads();

        // rescale and accumulate O += P V
        #pragma unroll
        for (int i = 0; i < 4; i++) {
            float f = sF[ty * 4 + i];
            #pragma unroll
            for (int j = 0; j < 4; j++) acc[i][j] *= f;
        }
        for (int k = 0; k < 64; k++) {
            float p[4], vv[4];
            #pragma unroll
            for (int i = 0; i < 4; i++) p[i]  = sS[(ty * 4 + i) * 65 + k];
            #pragma unroll
            for (int j = 0; j < 4; j++) vv[j] = sV[k * 65 + tx * 4 + j];
            #pragma unroll
            for (int i = 0; i < 4; i++)
                #pragma unroll
                for (int j = 0; j < 4; j++)
                    acc[i][j] = fmaf(p[i], vv[j], acc[i][j]);
        }
    }

    float* AOb = g_AO + (size_t)b * CDIM * CDIM;
    #pragma unroll
    for (int i = 0; i < 4; i++) {
        int r = ty * 4 + i;
        float inv = 1.0f / sL[r];
        #pragma unroll
        for (int j = 0; j < 4; j++)
            AOb[(size_t)(t0 + r) * CDIM + hb + tx * 4 + j] = acc[i][j] * inv;
    }
}

// ============================================================================
// Output projection: OUT[b][c][m] = sum_p AO[b][c][p] * Wo[m][p] + bo[m]
// 64x64 tile, BK=32, 4x4 per thread.
// ============================================================================
__global__ __launch_bounds__(256)
void proj_kernel(const float* __restrict__ Wo, const float* __restrict__ bo,
                 float* __restrict__ out)
{
    __shared__ float sA[32][65];
    __shared__ float sB[32][65];

    const int b  = blockIdx.z;
    const int c0 = blockIdx.x * 64;
    const int m0 = blockIdx.y * 64;
    const int t  = threadIdx.x;
    const int ty = t >> 4, tx = t & 15;

    const float* A = g_AO + (size_t)b * CDIM * CDIM;

    float acc[4][4];
    #pragma unroll
    for (int i = 0; i < 4; i++)
        #pragma unroll
        for (int j = 0; j < 4; j++) acc[i][j] = 0.f;

    for (int k0 = 0; k0 < CDIM; k0 += 32) {
        for (int idx = t; idx < 64 * 32; idx += 256) {
            int r  = idx >> 5;   // row within tile
            int kk = idx & 31;
            sA[kk][r] = A [(size_t)(c0 + r) * CDIM + k0 + kk];
            sB[kk][r] = Wo[(size_t)(m0 + r) * CDIM + k0 + kk];
        }
        __syncthreads();
        #pragma unroll
        for (int kk = 0; kk < 32; kk++) {
            float a[4], w[4];
            #pragma unroll
            for (int i = 0; i < 4; i++) a[i] = sA[kk][ty * 4 + i];
            #pragma unroll
            for (int j = 0; j < 4; j++) w[j] = sB[kk][tx * 4 + j];
            #pragma unroll
            for (int i = 0; i < 4; i++)
                #pragma unroll
                for (int j = 0; j < 4; j++)
                    acc[i][j] = fmaf(a[i], w[j], acc[i][j]);
        }
        __syncthreads();
    }

    #pragma unroll
    for (int i = 0; i < 4; i++) {
        int c = c0 + ty * 4 + i;
        #pragma unroll
        for (int j = 0; j < 4; j++) {
            int m = m0 + tx * 4 + j;
            out[(size_t)b * CDIM * CDIM + (size_t)c * CDIM + m] = acc[i][j] + bo[m];
        }
    }
}

// ============================================================================
extern "C" void kernel_launch(void* const* d_in, const int* in_sizes, int n_in,
                              void* d_out, int out_size)
{
    const float* q    = (const float*)d_in[0];
    const float* k    = (const float*)d_in[1];
    const float* v    = (const float*)d_in[2];
    const float* Wq   = (const float*)d_in[3];
    const float* bq   = (const float*)d_in[4];
    const float* Wk   = (const float*)d_in[5];
    const float* bk   = (const float*)d_in[6];
    const float* Wv   = (const float*)d_in[7];
    const float* bv   = (const float*)d_in[8];
    const float* Wo   = (const float*)d_in[9];
    const float* bo   = (const float*)d_in[10];
    const int*   mask = (const int*)d_in[11];

    // conv: 16 o-tiles x 4 h-tiles x (3 tensors * 8 batches)
    conv3x3_kernel<<<dim3(16, 4, 24), 256>>>(q, k, v, Wq, Wk, Wv, bq, bk, bv);

    // attention: 16 query tiles x 128 (b,head)
    const int att_smem = (4 * 64 * 65 + 3 * 64) * (int)sizeof(float);
    cudaFuncSetAttribute(attn_kernel, cudaFuncAttributeMaxDynamicSharedMemorySize,
                         att_smem);
    attn_kernel<<<dim3(16, 128), 256, att_smem>>>(mask);

    // projection: 16 c-tiles x 16 m-tiles x 8 batches
    proj_kernel<<<dim3(16, 16, 8), 256>>>(Wo, bo, (float*)d_out);
}

// round 4
// speedup vs baseline: 2.4461x; 2.4461x over previous
#include <cuda_runtime.h>
#include <cuda_bf16.h>

#define BDIM   8
#define CDIM   1024
#define HWDIM  32
#define NHEAD  16
#define HD     64
#define KDIM   9216          // 1024 * 9
#define NCHUNK 288           // KDIM / 32

// ---------------- scratch (static device globals; no allocations) ----------
__device__ float g_Qc[BDIM * CDIM * CDIM];
__device__ float g_Kc[BDIM * CDIM * CDIM];
__device__ float g_Vc[BDIM * CDIM * CDIM];
__device__ float g_AO[BDIM * CDIM * CDIM];
__device__ __nv_bfloat16 g_Bh[(size_t)24 * CDIM * KDIM];  // im2col hi
__device__ __nv_bfloat16 g_Bl[(size_t)24 * CDIM * KDIM];  // im2col lo
__device__ __nv_bfloat16 g_Wh[(size_t)3 * CDIM * KDIM];   // weights hi
__device__ __nv_bfloat16 g_Wl[(size_t)3 * CDIM * KDIM];   // weights lo

// ============================= PTX helpers ==================================
__device__ __forceinline__ unsigned smem_u32(const void* p) {
    unsigned a;
    asm("{ .reg .u64 t; cvta.to.shared.u64 t, %1; cvt.u32.u64 %0, t; }"
        : "=r"(a) : "l"(p));
    return a;
}
#define CP_ASYNC16(dst, src) \
    asm volatile("cp.async.cg.shared.global [%0], [%1], 16;" :: "r"(dst), "l"(src))
#define CP_COMMIT() asm volatile("cp.async.commit_group;" ::: "memory")
#define CP_WAIT1()  asm volatile("cp.async.wait_group 1;" ::: "memory")

__device__ __forceinline__ void mma_bf16(float& c0, float& c1, float& c2, float& c3,
                                         unsigned a0, unsigned a1, unsigned a2, unsigned a3,
                                         unsigned b0, unsigned b1) {
    asm volatile(
        "mma.sync.aligned.m16n8k16.row.col.f32.bf16.bf16.f32 "
        "{%0,%1,%2,%3}, {%4,%5,%6,%7}, {%8,%9}, {%0,%1,%2,%3};"
        : "+f"(c0), "+f"(c1), "+f"(c2), "+f"(c3)
        : "r"(a0), "r"(a1), "r"(a2), "r"(a3), "r"(b0), "r"(b1));
}

// ============================================================================
// Weight split: fp32 -> bf16 hi/lo pairs
// ============================================================================
__global__ __launch_bounds__(256)
void wsplit_kernel(const float* __restrict__ Wq, const float* __restrict__ Wk,
                   const float* __restrict__ Wv)
{
    const int tensor = blockIdx.y;
    const float* W = (tensor == 0) ? Wq : (tensor == 1) ? Wk : Wv;
    __nv_bfloat162* Wh2 = (__nv_bfloat162*)(g_Wh + (size_t)tensor * CDIM * KDIM);
    __nv_bfloat162* Wl2 = (__nv_bfloat162*)(g_Wl + (size_t)tensor * CDIM * KDIM);
    const float2* W2 = (const float2*)W;
    const size_t n2 = (size_t)CDIM * KDIM / 2;
    const size_t stride = (size_t)gridDim.x * 256;
    for (size_t i = (size_t)blockIdx.x * 256 + threadIdx.x; i < n2; i += stride) {
        float2 v = W2[i];
        __nv_bfloat16 hx = __float2bfloat16(v.x);
        __nv_bfloat16 hy = __float2bfloat16(v.y);
        __nv_bfloat162 h; h.x = hx; h.y = hy;
        __nv_bfloat162 l;
        l.x = __float2bfloat16(v.x - __bfloat162float(hx));
        l.y = __float2bfloat16(v.y - __bfloat162float(hy));
        Wh2[i] = h; Wl2[i] = l;
    }
}

// ============================================================================
// im2col + bf16 split, k-contiguous coalesced stores.
// Block: (pg: 128 p values, icg: 32 input channels, tb).
// ============================================================================
__global__ __launch_bounds__(256)
void im2col_kernel(const float* __restrict__ xq, const float* __restrict__ xk,
                   const float* __restrict__ xv)
{
    const int pg  = blockIdx.x;        // 0..7   (h0 = pg*4)
    const int icg = blockIdx.y;        // 0..31  (ic0 = icg*32)
    const int tb  = blockIdx.z;        // 0..23
    const int tensor = tb >> 3, b = tb & 7;
    const float* x = (tensor == 0) ? xq : (tensor == 1) ? xk : xv;

    const int h0  = pg * 4;
    const int ic0 = icg * 32;

    __shared__ float sx[32][6][34];    // [ic][gh-h0+1][gw+1]
    const int t = threadIdx.x;
    for (int idx = t; idx < 32 * 6 * 34; idx += 256) {
        int ic  = idx / 204;
        int rem = idx - ic * 204;
        int r   = rem / 34;
        int cc  = rem - r * 34;
        int gh  = h0 + r - 1;
        int gw  = cc - 1;
        float v = 0.f;
        if ((unsigned)gh < 32u && (unsigned)gw < 32u)
            v = x[((size_t)b * CDIM + ic0 + ic) * 1024 + gh * 32 + gw];
        sx[ic][r][cc] = v;
    }
    __syncthreads();

    __nv_bfloat16* dh = g_Bh + (size_t)tb * CDIM * KDIM;
    __nv_bfloat16* dl = g_Bl + (size_t)tb * CDIM * KDIM;

    for (int idx = t; idx < 128 * 288; idx += 256) {
        int pl = idx / 288;            // local p
        int kl = idx - pl * 288;       // local k (ic*9 + tap)
        int ic = kl / 9;
        int tap = kl - ic * 9;
        int ph = pl >> 5, w = pl & 31;
        float v = sx[ic][ph + tap / 3][w + tap % 3];
        __nv_bfloat16 h = __float2bfloat16(v);
        size_t off = (size_t)(pg * 128 + pl) * KDIM + ic0 * 9 + kl;
        dh[off] = h;
        dl[off] = __float2bfloat16(v - __bfloat162float(h));
    }
}

// ============================================================================
// Conv GEMM via mma.sync bf16 split. CTA tile 128x128, K chunk 32.
// smem tiles: row stride 40 bf16 (80B, cp.async 16B aligned), 4 tiles x 2 buf.
// Warp layout 2(m) x 4(n); warp tile 64x32.
// ============================================================================
#define TS    40                       // smem row stride in bf16
#define TSB   80                       // in bytes
#define TILEB (128 * TSB)              // 10240 bytes per tile
#define BUFB  (4 * TILEB)              // 40960 bytes per buffer

__device__ __forceinline__ void stage_chunk(
    unsigned sb, int buf,
    const __nv_bfloat16* __restrict__ Ah, const __nv_bfloat16* __restrict__ Al,
    const __nv_bfloat16* __restrict__ Bh, const __nv_bfloat16* __restrict__ Bl,
    int k0, int tid)
{
    const __nv_bfloat16* srcs[4] = {Ah, Al, Bh, Bl};
    #pragma unroll
    for (int tt = 0; tt < 4; tt++) {
        const __nv_bfloat16* s = srcs[tt];
        #pragma unroll 2
        for (int i = tid; i < 512; i += 256) {
            int row = i >> 2, c = i & 3;
            unsigned dst = sb + buf * BUFB + tt * TILEB + row * TSB + c * 16;
            const void* src = s + (size_t)row * KDIM + k0 + c * 8;
            CP_ASYNC16(dst, src);
        }
    }
}

__global__ __launch_bounds__(256)
void conv_mma_kernel(const float* __restrict__ bq, const float* __restrict__ bk,
                     const float* __restrict__ bv)
{
    extern __shared__ __align__(128) char smem[];
    const int tid = threadIdx.x;
    const int wid = tid >> 5, lid = tid & 31;
    const int g = lid >> 2, tig = lid & 3;
    const int wm = wid & 1, wn = wid >> 1;     // 2 x 4 warp grid

    const int tb = blockIdx.z;
    const int tensor = tb >> 3, b = tb & 7;
    const float* bias = (tensor == 0) ? bq : (tensor == 1) ? bk : bv;
    float* out = (tensor == 0) ? g_Qc : (tensor == 1) ? g_Kc : g_Vc;

    const int o0 = blockIdx.x * 128;
    const int p0 = blockIdx.y * 128;

    const __nv_bfloat16* Ah = g_Wh + (size_t)tensor * CDIM * KDIM + (size_t)o0 * KDIM;
    const __nv_bfloat16* Al = g_Wl + (size_t)tensor * CDIM * KDIM + (size_t)o0 * KDIM;
    const __nv_bfloat16* Bh = g_Bh + (size_t)tb * CDIM * KDIM + (size_t)p0 * KDIM;
    const __nv_bfloat16* Bl = g_Bl + (size_t)tb * CDIM * KDIM + (size_t)p0 * KDIM;

    const unsigned sb = smem_u32(smem);

    float acc[4][4][4];
    #pragma unroll
    for (int i = 0; i < 4; i++)
        #pragma unroll
        for (int j = 0; j < 4; j++)
            #pragma unroll
            for (int r = 0; r < 4; r++) acc[i][j][r] = 0.f;

    stage_chunk(sb, 0, Ah, Al, Bh, Bl, 0, tid);
    CP_COMMIT();

    for (int c = 0; c < NCHUNK; c++) {
        if (c + 1 < NCHUNK)
            stage_chunk(sb, (c + 1) & 1, Ah, Al, Bh, Bl, (c + 1) * 32, tid);
        CP_COMMIT();
        CP_WAIT1();
        __syncthreads();

        const unsigned base = sb + (c & 1) * BUFB;
        const unsigned aho = base + 0 * TILEB;
        const unsigned alo = base + 1 * TILEB;
        const unsigned bho = base + 2 * TILEB;
        const unsigned blo = base + 3 * TILEB;

        #pragma unroll
        for (int s = 0; s < 2; s++) {
            unsigned aH[4][4], aL[4][4], bH[4][2], bL[4][2];
            #pragma unroll
            for (int mt = 0; mt < 4; mt++) {
                unsigned ro = (wm * 64 + mt * 16 + g) * TSB + (s * 16 + tig * 2) * 2;
                asm volatile("ld.shared.b32 %0, [%1];" : "=r"(aH[mt][0]) : "r"(aho + ro));
                asm volatile("ld.shared.b32 %0, [%1];" : "=r"(aH[mt][1]) : "r"(aho + ro + 8 * TSB));
                asm volatile("ld.shared.b32 %0, [%1];" : "=r"(aH[mt][2]) : "r"(aho + ro + 16));
                asm volatile("ld.shared.b32 %0, [%1];" : "=r"(aH[mt][3]) : "r"(aho + ro + 8 * TSB + 16));
                asm volatile("ld.shared.b32 %0, [%1];" : "=r"(aL[mt][0]) : "r"(alo + ro));
                asm volatile("ld.shared.b32 %0, [%1];" : "=r"(aL[mt][1]) : "r"(alo + ro + 8 * TSB));
                asm volatile("ld.shared.b32 %0, [%1];" : "=r"(aL[mt][2]) : "r"(alo + ro + 16));
                asm volatile("ld.shared.b32 %0, [%1];" : "=r"(aL[mt][3]) : "r"(alo + ro + 8 * TSB + 16));
            }
            #pragma unroll
            for (int nt = 0; nt < 4; nt++) {
                unsigned ro = (wn * 32 + nt * 8 + g) * TSB + (s * 16 + tig * 2) * 2;
                asm volatile("ld.shared.b32 %0, [%1];" : "=r"(bH[nt][0]) : "r"(bho + ro));
                asm volatile("ld.shared.b32 %0, [%1];" : "=r"(bH[nt][1]) : "r"(bho + ro + 16));
                asm volatile("ld.shared.b32 %0, [%1];" : "=r"(bL[nt][0]) : "r"(blo + ro));
                asm volatile("ld.shared.b32 %0, [%1];" : "=r"(bL[nt][1]) : "r"(blo + ro + 16));
            }
            #pragma unroll
            for (int mt = 0; mt < 4; mt++)
                #pragma unroll
                for (int nt = 0; nt < 4; nt++) {
                    float* c4 = acc[mt][nt];
                    mma_bf16(c4[0], c4[1], c4[2], c4[3],
                             aH[mt][0], aH[mt][1], aH[mt][2], aH[mt][3],
                             bH[nt][0], bH[nt][1]);
                    mma_bf16(c4[0], c4[1], c4[2], c4[3],
                             aH[mt][0], aH[mt][1], aH[mt][2], aH[mt][3],
                             bL[nt][0], bL[nt][1]);
                    mma_bf16(c4[0], c4[1], c4[2], c4[3],
                             aL[mt][0], aL[mt][1], aL[mt][2], aL[mt][3],
                             bH[nt][0], bH[nt][1]);
                }
        }
        __syncthreads();
    }

    // epilogue: D[row][col] (+bias) -> out[b][o0+row][p0+col]
    #pragma unroll
    for (int mt = 0; mt < 4; mt++) {
        #pragma unroll
        for (int rr = 0; rr < 2; rr++) {
            int row = wm * 64 + mt * 16 + g + rr * 8;
            float bv_ = bias[o0 + row];
            float* orow = out + ((size_t)b * CDIM + o0 + row) * CDIM + p0;
            #pragma unroll
            for (int nt = 0; nt < 4; nt++) {
                int col = wn * 32 + nt * 8 + tig * 2;
                float2 vv;
                vv.x = acc[mt][nt][rr * 2 + 0] + bv_;
                vv.y = acc[mt][nt][rr * 2 + 1] + bv_;
                *(float2*)(orow + col) = vv;
            }
        }
    }
}

// ============================================================================
// Flash-style attention (unchanged, known-good)
// ============================================================================
__global__ __launch_bounds__(256)
void attn_kernel(const int* __restrict__ mask)
{
    extern __shared__ float smemf[];
    float* sQ = smemf;
    float* sK = sQ + 64 * 65;
    float* sV = sK + 64 * 65;
    float* sS = sV + 64 * 65;
    float* sM = sS + 64 * 65;
    float* sL = sM + 64;
    float* sF = sL + 64;

    const int bh   = blockIdx.y;
    const int b    = bh >> 4;
    const int head = bh & 15;
    const int t0   = blockIdx.x * 64;

    const int t  = threadIdx.x;
    const int ty = t >> 4;
    const int tx = t & 15;

    const float* Qb = g_Qc + (size_t)b * CDIM * CDIM;
    const float* Kb = g_Kc + (size_t)b * CDIM * CDIM;
    const float* Vb = g_Vc + (size_t)b * CDIM * CDIM;
    const int    hb = head * HD;

    for (int idx = t; idx < 64 * 64; idx += 256) {
        int r = idx >> 6, k = idx & 63;
        sQ[r * 65 + k] = Qb[(size_t)(t0 + r) * CDIM + hb + k];
    }
    if (t < 64) { sM[t] = -1e30f; sL[t] = 0.f; }

    float acc[4][4];
    #pragma unroll
    for (int i = 0; i < 4; i++)
        #pragma unroll
        for (int j = 0; j < 4; j++) acc[i][j] = 0.f;

    const float scale = 0.125f;

    for (int sbk = 0; sbk < 16; sbk++) {
        const int s0 = sbk * 64;
        __syncthreads();
        for (int idx = t; idx < 64 * 64; idx += 256) {
            int r = idx >> 6, k = idx & 63;
            sK[r * 65 + k] = Kb[(size_t)(s0 + r) * CDIM + hb + k];
            sV[r * 65 + k] = Vb[(size_t)(s0 + r) * CDIM + hb + k];
        }
        __syncthreads();

        float sv[4][4];
        #pragma unroll
        for (int i = 0; i < 4; i++)
            #pragma unroll
            for (int j = 0; j < 4; j++) sv[i][j] = 0.f;
        for (int k = 0; k < 64; k++) {
            float aq[4], bk_[4];
            #pragma unroll
            for (int i = 0; i < 4; i++) aq[i]  = sQ[(ty * 4 + i) * 65 + k];
            #pragma unroll
            for (int j = 0; j < 4; j++) bk_[j] = sK[(tx * 4 + j) * 65 + k];
            #pragma unroll
            for (int i = 0; i < 4; i++)
                #pragma unroll
                for (int j = 0; j < 4; j++)
                    sv[i][j] = fmaf(aq[i], bk_[j], sv[i][j]);
        }
        #pragma unroll
        for (int i = 0; i < 4; i++) {
            int tg = t0 + ty * 4 + i;
            #pragma unroll
            for (int j = 0; j < 4; j++) {
                int sg = s0 + tx * 4 + j;
                float val = sv[i][j] * scale;
                int mv = mask[(size_t)b * CDIM * CDIM + (size_t)tg * CDIM + sg];
                if (mv == 0) val = -1e9f;
                sS[(ty * 4 + i) * 65 + tx * 4 + j] = val;
            }
        }
        __syncthreads();

        if (t < 64) {
            float m_old = sM[t];
            float mx = m_old;
            for (int s = 0; s < 64; s++) mx = fmaxf(mx, sS[t * 65 + s]);
            float f = __expf(m_old - mx);
            float sum = 0.f;
            for (int s = 0; s < 64; s++) {
                float e = __expf(sS[t * 65 + s] - mx);
                sS[t * 65 + s] = e;
                sum += e;
            }
            sL[t] = sL[t] * f + sum;
            sM[t] = mx;
            sF[t] = f;
        }
        __syncthreads();

        #pragma unroll
        for (int i = 0; i < 4; i++) {
            float f = sF[ty * 4 + i];
            #pragma unroll
            for (int j = 0; j < 4; j++) acc[i][j] *= f;
        }
        for (int k = 0; k < 64; k++) {
            float p[4], vv[4];
            #pragma unroll
            for (int i = 0; i < 4; i++) p[i]  = sS[(ty * 4 + i) * 65 + k];
            #pragma unroll
            for (int j = 0; j < 4; j++) vv[j] = sV[k * 65 + tx * 4 + j];
            #pragma unroll
            for (int i = 0; i < 4; i++)
                #pragma unroll
                for (int j = 0; j < 4; j++)
                    acc[i][j] = fmaf(p[i], vv[j], acc[i][j]);
        }
    }

    float* AOb = g_AO + (size_t)b * CDIM * CDIM;
    #pragma unroll
    for (int i = 0; i < 4; i++) {
        int r = ty * 4 + i;
        float inv = 1.0f / sL[r];
        #pragma unroll
        for (int j = 0; j < 4; j++)
            AOb[(size_t)(t0 + r) * CDIM + hb + tx * 4 + j] = acc[i][j] * inv;
    }
}

// ============================================================================
// Output projection (unchanged, known-good)
// ============================================================================
__global__ __launch_bounds__(256)
void proj_kernel(const float* __restrict__ Wo, const float* __restrict__ bo,
                 float* __restrict__ out)
{
    __shared__ float sA[32][65];
    __shared__ float sB[32][65];

    const int b  = blockIdx.z;
    const int c0 = blockIdx.x * 64;
    const int m0 = blockIdx.y * 64;
    const int t  = threadIdx.x;
    const int ty = t >> 4, tx = t & 15;

    const float* A = g_AO + (size_t)b * CDIM * CDIM;

    float acc[4][4];
    #pragma unroll
    for (int i = 0; i < 4; i++)
        #pragma unroll
        for (int j = 0; j < 4; j++) acc[i][j] = 0.f;

    for (int k0 = 0; k0 < CDIM; k0 += 32) {
        for (int idx = t; idx < 64 * 32; idx += 256) {
            int r  = idx >> 5;
            int kk = idx & 31;
            sA[kk][r] = A [(size_t)(c0 + r) * CDIM + k0 + kk];
            sB[kk][r] = Wo[(size_t)(m0 + r) * CDIM + k0 + kk];
        }
        __syncthreads();
        #pragma unroll
        for (int kk = 0; kk < 32; kk++) {
            float a[4], w[4];
            #pragma unroll
            for (int i = 0; i < 4; i++) a[i] = sA[kk][ty * 4 + i];
            #pragma unroll
            for (int j = 0; j < 4; j++) w[j] = sB[kk][tx * 4 + j];
            #pragma unroll
            for (int i = 0; i < 4; i++)
                #pragma unroll
                for (int j = 0; j < 4; j++)
                    acc[i][j] = fmaf(a[i], w[j], acc[i][j]);
        }
        __syncthreads();
    }

    #pragma unroll
    for (int i = 0; i < 4; i++) {
        int c = c0 + ty * 4 + i;
        #pragma unroll
        for (int j = 0; j < 4; j++) {
            int m = m0 + tx * 4 + j;
            out[(size_t)b * CDIM * CDIM + (size_t)c * CDIM + m] = acc[i][j] + bo[m];
        }
    }
}

// ============================================================================
extern "C" void kernel_launch(void* const* d_in, const int* in_sizes, int n_in,
                              void* d_out, int out_size)
{
    const float* q    = (const float*)d_in[0];
    const float* k    = (const float*)d_in[1];
    const float* v    = (const float*)d_in[2];
    const float* Wq   = (const float*)d_in[3];
    const float* bq   = (const float*)d_in[4];
    const float* Wk   = (const float*)d_in[5];
    const float* bk   = (const float*)d_in[6];
    const float* Wv   = (const float*)d_in[7];
    const float* bv   = (const float*)d_in[8];
    const float* Wo   = (const float*)d_in[9];
    const float* bo   = (const float*)d_in[10];
    const int*   mask = (const int*)d_in[11];

    // 1) split weights into bf16 hi/lo
    wsplit_kernel<<<dim3(1024, 3), 256>>>(Wq, Wk, Wv);

    // 2) im2col with bf16 split (coalesced k-major stores)
    im2col_kernel<<<dim3(8, 32, 24), 256>>>(q, k, v);

    // 3) conv as mma.sync bf16-split GEMM
    const int gemm_smem = 2 * BUFB;     // 81920 B
    cudaFuncSetAttribute(conv_mma_kernel,
                         cudaFuncAttributeMaxDynamicSharedMemorySize, gemm_smem);
    conv_mma_kernel<<<dim3(8, 8, 24), 256, gemm_smem>>>(bq, bk, bv);

    // 4) attention
    const int att_smem = (4 * 64 * 65 + 3 * 64) * (int)sizeof(float);
    cudaFuncSetAttribute(attn_kernel, cudaFuncAttributeMaxDynamicSharedMemorySize,
                         att_smem);
    attn_kernel<<<dim3(16, 128), 256, att_smem>>>(mask);

    // 5) projection
    proj_kernel<<<dim3(16, 16, 8), 256>>>(Wo, bo, (float*)d_out);
}

// round 5
// speedup vs baseline: 3.0420x; 1.2436x over previous
#include <cuda_runtime.h>
#include <cuda_bf16.h>

#define BDIM   8
#define CDIM   1024
#define HWDIM  32
#define NHEAD  16
#define HD     64
#define KDIM   9216          // 1024 * 9
#define NCHUNK 288           // KDIM / 32

// ---------------- scratch (static device globals; no allocations) ----------
__device__ __nv_bfloat16 g_Bh[(size_t)24 * CDIM * KDIM];  // im2col hi
__device__ __nv_bfloat16 g_Bl[(size_t)24 * CDIM * KDIM];  // im2col lo
__device__ __nv_bfloat16 g_Wh[(size_t)3 * CDIM * KDIM];   // conv weights hi
__device__ __nv_bfloat16 g_Wl[(size_t)3 * CDIM * KDIM];   // conv weights lo
// conv outputs as bf16 hi/lo (attention inputs), layout [b][token][1024]
__device__ __nv_bfloat16 g_Qh[BDIM * CDIM * CDIM], g_Ql[BDIM * CDIM * CDIM];
__device__ __nv_bfloat16 g_Kh[BDIM * CDIM * CDIM], g_Kl[BDIM * CDIM * CDIM];
__device__ __nv_bfloat16 g_Vh[BDIM * CDIM * CDIM], g_Vl[BDIM * CDIM * CDIM];
// attention output hi/lo, layout [b][token][1024]
__device__ __nv_bfloat16 g_AOh[BDIM * CDIM * CDIM], g_AOl[BDIM * CDIM * CDIM];
// Wo split
__device__ __nv_bfloat16 g_Woh[CDIM * CDIM], g_Wol[CDIM * CDIM];

// ============================= PTX helpers ==================================
__device__ __forceinline__ unsigned smem_u32(const void* p) {
    unsigned a;
    asm("{ .reg .u64 t; cvta.to.shared.u64 t, %1; cvt.u32.u64 %0, t; }"
        : "=r"(a) : "l"(p));
    return a;
}
#define CP_ASYNC16(dst, src) \
    asm volatile("cp.async.cg.shared.global [%0], [%1], 16;" :: "r"(dst), "l"(src))
#define CP_COMMIT() asm volatile("cp.async.commit_group;" ::: "memory")
#define CP_WAIT1()  asm volatile("cp.async.wait_group 1;" ::: "memory")

__device__ __forceinline__ void mma_bf16(float& c0, float& c1, float& c2, float& c3,
                                         unsigned a0, unsigned a1, unsigned a2, unsigned a3,
                                         unsigned b0, unsigned b1) {
    asm volatile(
        "mma.sync.aligned.m16n8k16.row.col.f32.bf16.bf16.f32 "
        "{%0,%1,%2,%3}, {%4,%5,%6,%7}, {%8,%9}, {%0,%1,%2,%3};"
        : "+f"(c0), "+f"(c1), "+f"(c2), "+f"(c3)
        : "r"(a0), "r"(a1), "r"(a2), "r"(a3), "r"(b0), "r"(b1));
}
#define LDSM4(r, a) \
    asm volatile("ldmatrix.sync.aligned.m8n8.x4.shared.b16 {%0,%1,%2,%3}, [%4];" \
        : "=r"((r)[0]), "=r"((r)[1]), "=r"((r)[2]), "=r"((r)[3]) : "r"(a))
#define LDSM4T(r, a) \
    asm volatile("ldmatrix.sync.aligned.m8n8.x4.trans.shared.b16 {%0,%1,%2,%3}, [%4];" \
        : "=r"((r)[0]), "=r"((r)[1]), "=r"((r)[2]), "=r"((r)[3]) : "r"(a))

__device__ __forceinline__ unsigned pack_bf2(float a, float b) {
    __nv_bfloat162 t = __floats2bfloat162_rn(a, b);
    return *reinterpret_cast<unsigned*>(&t);
}

// ============================================================================
// Weight split: fp32 -> bf16 hi/lo (conv weights + Wo)
// ============================================================================
__global__ __launch_bounds__(256)
void wsplit_kernel(const float* __restrict__ Wq, const float* __restrict__ Wk,
                   const float* __restrict__ Wv, const float* __restrict__ Wo)
{
    const int tensor = blockIdx.y;
    const float* W;
    __nv_bfloat162 *Wh2, *Wl2;
    size_t n2;
    if (tensor < 3) {
        W = (tensor == 0) ? Wq : (tensor == 1) ? Wk : Wv;
        Wh2 = (__nv_bfloat162*)(g_Wh + (size_t)tensor * CDIM * KDIM);
        Wl2 = (__nv_bfloat162*)(g_Wl + (size_t)tensor * CDIM * KDIM);
        n2 = (size_t)CDIM * KDIM / 2;
    } else {
        W = Wo;
        Wh2 = (__nv_bfloat162*)g_Woh;
        Wl2 = (__nv_bfloat162*)g_Wol;
        n2 = (size_t)CDIM * CDIM / 2;
    }
    const float2* W2 = (const float2*)W;
    const size_t stride = (size_t)gridDim.x * 256;
    for (size_t i = (size_t)blockIdx.x * 256 + threadIdx.x; i < n2; i += stride) {
        float2 v = W2[i];
        __nv_bfloat162 h = __floats2bfloat162_rn(v.x, v.y);
        __nv_bfloat162 l = __floats2bfloat162_rn(v.x - __low2float(h),
                                                 v.y - __high2float(h));
        Wh2[i] = h; Wl2[i] = l;
    }
}

// ============================================================================
// im2col + bf16 split, k-contiguous coalesced stores.
// ============================================================================
__global__ __launch_bounds__(256)
void im2col_kernel(const float* __restrict__ xq, const float* __restrict__ xk,
                   const float* __restrict__ xv)
{
    const int pg  = blockIdx.x;
    const int icg = blockIdx.y;
    const int tb  = blockIdx.z;
    const int tensor = tb >> 3, b = tb & 7;
    const float* x = (tensor == 0) ? xq : (tensor == 1) ? xk : xv;

    const int h0  = pg * 4;
    const int ic0 = icg * 32;

    __shared__ float sx[32][6][34];
    const int t = threadIdx.x;
    for (int idx = t; idx < 32 * 6 * 34; idx += 256) {
        int ic  = idx / 204;
        int rem = idx - ic * 204;
        int r   = rem / 34;
        int cc  = rem - r * 34;
        int gh  = h0 + r - 1;
        int gw  = cc - 1;
        float v = 0.f;
        if ((unsigned)gh < 32u && (unsigned)gw < 32u)
            v = x[((size_t)b * CDIM + ic0 + ic) * 1024 + gh * 32 + gw];
        sx[ic][r][cc] = v;
    }
    __syncthreads();

    __nv_bfloat16* dh = g_Bh + (size_t)tb * CDIM * KDIM;
    __nv_bfloat16* dl = g_Bl + (size_t)tb * CDIM * KDIM;

    for (int idx = t; idx < 128 * 288; idx += 256) {
        int pl = idx / 288;
        int kl = idx - pl * 288;
        int ic = kl / 9;
        int tap = kl - ic * 9;
        int ph = pl >> 5, w = pl & 31;
        float v = sx[ic][ph + tap / 3][w + tap % 3];
        __nv_bfloat16 h = __float2bfloat16(v);
        size_t off = (size_t)(pg * 128 + pl) * KDIM + ic0 * 9 + kl;
        dh[off] = h;
        dl[off] = __float2bfloat16(v - __bfloat162float(h));
    }
}

// ============================================================================
// GEMM staging (shared by conv & proj): 4 tiles x 128 rows x 32 k, cp.async
// ============================================================================
#define TS    40
#define TSB   80
#define TILEB (128 * TSB)
#define BUFB  (4 * TILEB)

__device__ __forceinline__ void stage_chunk(
    unsigned sb, int buf,
    const __nv_bfloat16* __restrict__ Ah, const __nv_bfloat16* __restrict__ Al,
    const __nv_bfloat16* __restrict__ Bh, const __nv_bfloat16* __restrict__ Bl,
    int k0, int tid, int kdim)
{
    const __nv_bfloat16* srcs[4] = {Ah, Al, Bh, Bl};
    #pragma unroll
    for (int tt = 0; tt < 4; tt++) {
        const __nv_bfloat16* s = srcs[tt];
        #pragma unroll 2
        for (int i = tid; i < 512; i += 256) {
            int row = i >> 2, c = i & 3;
            unsigned dst = sb + buf * BUFB + tt * TILEB + row * TSB + c * 16;
            const void* src = s + (size_t)row * kdim + k0 + c * 8;
            CP_ASYNC16(dst, src);
        }
    }
}

// ============================================================================
// GEMM inner compute (one K=32 chunk), 8 warps 2x4, warp 64x32
// ============================================================================
__device__ __forceinline__ void gemm_chunk(unsigned base, int wm, int wn,
                                           int g, int tig, float acc[4][4][4])
{
    const unsigned aho = base + 0 * TILEB;
    const unsigned alo = base + 1 * TILEB;
    const unsigned bho = base + 2 * TILEB;
    const unsigned blo = base + 3 * TILEB;

    #pragma unroll
    for (int s = 0; s < 2; s++) {
        unsigned aH[4][4], aL[4][4], bH[4][2], bL[4][2];
        #pragma unroll
        for (int mt = 0; mt < 4; mt++) {
            unsigned ro = (wm * 64 + mt * 16 + g) * TSB + (s * 16 + tig * 2) * 2;
            asm volatile("ld.shared.b32 %0, [%1];" : "=r"(aH[mt][0]) : "r"(aho + ro));
            asm volatile("ld.shared.b32 %0, [%1];" : "=r"(aH[mt][1]) : "r"(aho + ro + 8 * TSB));
            asm volatile("ld.shared.b32 %0, [%1];" : "=r"(aH[mt][2]) : "r"(aho + ro + 16));
            asm volatile("ld.shared.b32 %0, [%1];" : "=r"(aH[mt][3]) : "r"(aho + ro + 8 * TSB + 16));
            asm volatile("ld.shared.b32 %0, [%1];" : "=r"(aL[mt][0]) : "r"(alo + ro));
            asm volatile("ld.shared.b32 %0, [%1];" : "=r"(aL[mt][1]) : "r"(alo + ro + 8 * TSB));
            asm volatile("ld.shared.b32 %0, [%1];" : "=r"(aL[mt][2]) : "r"(alo + ro + 16));
            asm volatile("ld.shared.b32 %0, [%1];" : "=r"(aL[mt][3]) : "r"(alo + ro + 8 * TSB + 16));
        }
        #pragma unroll
        for (int nt = 0; nt < 4; nt++) {
            unsigned ro = (wn * 32 + nt * 8 + g) * TSB + (s * 16 + tig * 2) * 2;
            asm volatile("ld.shared.b32 %0, [%1];" : "=r"(bH[nt][0]) : "r"(bho + ro));
            asm volatile("ld.shared.b32 %0, [%1];" : "=r"(bH[nt][1]) : "r"(bho + ro + 16));
            asm volatile("ld.shared.b32 %0, [%1];" : "=r"(bL[nt][0]) : "r"(blo + ro));
            asm volatile("ld.shared.b32 %0, [%1];" : "=r"(bL[nt][1]) : "r"(blo + ro + 16));
        }
        #pragma unroll
        for (int mt = 0; mt < 4; mt++)
            #pragma unroll
            for (int nt = 0; nt < 4; nt++) {
                float* c4 = acc[mt][nt];
                mma_bf16(c4[0], c4[1], c4[2], c4[3],
                         aH[mt][0], aH[mt][1], aH[mt][2], aH[mt][3],
                         bH[nt][0], bH[nt][1]);
                mma_bf16(c4[0], c4[1], c4[2], c4[3],
                         aH[mt][0], aH[mt][1], aH[mt][2], aH[mt][3],
                         bL[nt][0], bL[nt][1]);
                mma_bf16(c4[0], c4[1], c4[2], c4[3],
                         aL[mt][0], aL[mt][1], aL[mt][2], aL[mt][3],
                         bH[nt][0], bH[nt][1]);
            }
    }
}

// ============================================================================
// Conv GEMM: out = W * Bcol^T, epilogue writes bf16 hi/lo Q/K/V.
// ============================================================================
__global__ __launch_bounds__(256)
void conv_mma_kernel(const float* __restrict__ bq, const float* __restrict__ bk,
                     const float* __restrict__ bv)
{
    extern __shared__ __align__(128) char smem[];
    const int tid = threadIdx.x;
    const int wid = tid >> 5, lid = tid & 31;
    const int g = lid >> 2, tig = lid & 3;
    const int wm = wid & 1, wn = wid >> 1;

    const int tb = blockIdx.z;
    const int tensor = tb >> 3, b = tb & 7;
    const float* bias = (tensor == 0) ? bq : (tensor == 1) ? bk : bv;
    __nv_bfloat16* outh = (tensor == 0) ? g_Qh : (tensor == 1) ? g_Kh : g_Vh;
    __nv_bfloat16* outl = (tensor == 0) ? g_Ql : (tensor == 1) ? g_Kl : g_Vl;

    const int o0 = blockIdx.x * 128;
    const int p0 = blockIdx.y * 128;

    const __nv_bfloat16* Ah = g_Wh + (size_t)tensor * CDIM * KDIM + (size_t)o0 * KDIM;
    const __nv_bfloat16* Al = g_Wl + (size_t)tensor * CDIM * KDIM + (size_t)o0 * KDIM;
    const __nv_bfloat16* Bh = g_Bh + (size_t)tb * CDIM * KDIM + (size_t)p0 * KDIM;
    const __nv_bfloat16* Bl = g_Bl + (size_t)tb * CDIM * KDIM + (size_t)p0 * KDIM;

    const unsigned sb = smem_u32(smem);

    float acc[4][4][4];
    #pragma unroll
    for (int i = 0; i < 4; i++)
        #pragma unroll
        for (int j = 0; j < 4; j++)
            #pragma unroll
            for (int r = 0; r < 4; r++) acc[i][j][r] = 0.f;

    stage_chunk(sb, 0, Ah, Al, Bh, Bl, 0, tid, KDIM);
    CP_COMMIT();

    for (int c = 0; c < NCHUNK; c++) {
        if (c + 1 < NCHUNK)
            stage_chunk(sb, (c + 1) & 1, Ah, Al, Bh, Bl, (c + 1) * 32, tid, KDIM);
        CP_COMMIT();
        CP_WAIT1();
        __syncthreads();
        gemm_chunk(sb + (c & 1) * BUFB, wm, wn, g, tig, acc);
        __syncthreads();
    }

    // epilogue: bf16 hi/lo split -> [b][o][p]
    #pragma unroll
    for (int mt = 0; mt < 4; mt++) {
        #pragma unroll
        for (int rr = 0; rr < 2; rr++) {
            int row = wm * 64 + mt * 16 + g + rr * 8;
            float bv_ = bias[o0 + row];
            size_t ro = ((size_t)b * CDIM + o0 + row) * CDIM + p0;
            #pragma unroll
            for (int nt = 0; nt < 4; nt++) {
                int col = wn * 32 + nt * 8 + tig * 2;
                float v0 = acc[mt][nt][rr * 2 + 0] + bv_;
                float v1 = acc[mt][nt][rr * 2 + 1] + bv_;
                __nv_bfloat162 h2 = __floats2bfloat162_rn(v0, v1);
                __nv_bfloat162 l2 = __floats2bfloat162_rn(v0 - __low2float(h2),
                                                          v1 - __high2float(h2));
                *(__nv_bfloat162*)(outh + ro + col) = h2;
                *(__nv_bfloat162*)(outl + ro + col) = l2;
            }
        }
    }
}

// ============================================================================
// Projection GEMM: out[b][c][m] = AO[c][:] . Wo[m][:] + bo[m], fp32 out.
// ============================================================================
__global__ __launch_bounds__(256)
void proj_mma_kernel(const float* __restrict__ bo, float* __restrict__ out)
{
    extern __shared__ __align__(128) char smem[];
    const int tid = threadIdx.x;
    const int wid = tid >> 5, lid = tid & 31;
    const int g = lid >> 2, tig = lid & 3;
    const int wm = wid & 1, wn = wid >> 1;

    const int b  = blockIdx.z;
    const int c0 = blockIdx.x * 128;
    const int m0 = blockIdx.y * 128;

    const __nv_bfloat16* Ah = g_AOh + ((size_t)b * CDIM + c0) * CDIM;
    const __nv_bfloat16* Al = g_AOl + ((size_t)b * CDIM + c0) * CDIM;
    const __nv_bfloat16* Bh = g_Woh + (size_t)m0 * CDIM;
    const __nv_bfloat16* Bl = g_Wol + (size_t)m0 * CDIM;

    const unsigned sb = smem_u32(smem);

    float acc[4][4][4];
    #pragma unroll
    for (int i = 0; i < 4; i++)
        #pragma unroll
        for (int j = 0; j < 4; j++)
            #pragma unroll
            for (int r = 0; r < 4; r++) acc[i][j][r] = 0.f;

    stage_chunk(sb, 0, Ah, Al, Bh, Bl, 0, tid, CDIM);
    CP_COMMIT();

    for (int c = 0; c < 32; c++) {
        if (c + 1 < 32)
            stage_chunk(sb, (c + 1) & 1, Ah, Al, Bh, Bl, (c + 1) * 32, tid, CDIM);
        CP_COMMIT();
        CP_WAIT1();
        __syncthreads();
        gemm_chunk(sb + (c & 1) * BUFB, wm, wn, g, tig, acc);
        __syncthreads();
    }

    #pragma unroll
    for (int mt = 0; mt < 4; mt++) {
        #pragma unroll
        for (int rr = 0; rr < 2; rr++) {
            int row = wm * 64 + mt * 16 + g + rr * 8;
            float* orow = out + ((size_t)b * CDIM + c0 + row) * CDIM + m0;
            #pragma unroll
            for (int nt = 0; nt < 4; nt++) {
                int col = wn * 32 + nt * 8 + tig * 2;
                float2 vv;
                vv.x = acc[mt][nt][rr * 2 + 0] + bo[m0 + col];
                vv.y = acc[mt][nt][rr * 2 + 1] + bo[m0 + col + 1];
                *(float2*)(orow + col) = vv;
            }
        }
    }
}

// ============================================================================
// Attention via mma.sync, split bf16, flash-style online softmax.
// CTA: 128 q rows x one (b,head). 8 warps, warp = 16q x 64s (full rows).
// smem: sQh[128x64]@ATS, sQl, then 2 KV buffers (Kh,Kl,Vh,Vl 64x64 each).
// ============================================================================
#define ATS      144                    // bf16 row stride bytes (64*2 + 16 pad)
#define ATT_QL   18432                  // 128*144
#define ATT_BUF  36864
#define ATT_BUFSZ 36864                 // 4 * 64*144
#define ATT_SMEM (ATT_BUF + 2 * ATT_BUFSZ)   // 110592

__global__ __launch_bounds__(256)
void attn_mma_kernel(const int* __restrict__ mask)
{
    extern __shared__ __align__(128) char sm[];
    const unsigned sb = smem_u32(sm);
    const int tid = threadIdx.x, wid = tid >> 5, lane = tid & 31;
    const int bh = blockIdx.y, b = bh >> 4, head = bh & 15, hb = head * HD;
    const int t0 = blockIdx.x * 128;

    const size_t rowbase = (size_t)b * CDIM * CDIM + hb;

    // stage Q hi/lo (128 rows x 64 cols)
    for (int i = tid; i < 2048; i += 256) {
        int t = i >> 10, r = (i >> 3) & 127, c = i & 7;
        const __nv_bfloat16* src = (t ? g_Ql : g_Qh) + rowbase + (size_t)(t0 + r) * CDIM + c * 8;
        CP_ASYNC16(sb + t * ATT_QL + r * ATS + c * 16, src);
    }
    // stage KV tile 0
    for (int i = tid; i < 2048; i += 256) {
        int t = i >> 9, r = (i >> 3) & 63, c = i & 7;
        const __nv_bfloat16* base = (t == 0) ? g_Kh : (t == 1) ? g_Kl
                                  : (t == 2) ? g_Vh : g_Vl;
        CP_ASYNC16(sb + ATT_BUF + t * 9216 + r * ATS + c * 16,
                   base + rowbase + (size_t)r * CDIM + c * 8);
    }
    CP_COMMIT();

    float oacc[8][4];
    #pragma unroll
    for (int i = 0; i < 8; i++)
        #pragma unroll
        for (int j = 0; j < 4; j++) oacc[i][j] = 0.f;
    float mrun0 = -1e30f, mrun1 = -1e30f, lrun0 = 0.f, lrun1 = 0.f;

    const int qrow = wid * 16 + (lane & 15);
    const unsigned qcoloff = ((lane >> 4) & 1) * 16;      // bytes
    const unsigned kro = ((lane >> 4) & 1) * 8 + (lane & 7);
    const unsigned kco = ((lane >> 3) & 1) * 16;          // bytes
    const unsigned vro = ((lane >> 3) & 1) * 8 + (lane & 7);
    const unsigned vco = ((lane >> 4) & 1) * 16;          // bytes

    for (int s = 0; s < 16; s++) {
        __syncthreads();
        if (s + 1 < 16) {
            unsigned bufb = sb + ATT_BUF + ((s + 1) & 1) * ATT_BUFSZ;
            for (int i = tid; i < 2048; i += 256) {
                int t = i >> 9, r = (i >> 3) & 63, c = i & 7;
                const __nv_bfloat16* base = (t == 0) ? g_Kh : (t == 1) ? g_Kl
                                          : (t == 2) ? g_Vh : g_Vl;
                CP_ASYNC16(bufb + t * 9216 + r * ATS + c * 16,
                           base + rowbase + (size_t)((s + 1) * 64 + r) * CDIM + c * 8);
            }
        }
        CP_COMMIT();
        CP_WAIT1();
        __syncthreads();

        const unsigned kb = sb + ATT_BUF + (s & 1) * ATT_BUFSZ;

        // ---- S = Q K^T (split) ----
        float sacc[8][4];
        #pragma unroll
        for (int i = 0; i < 8; i++)
            #pragma unroll
            for (int j = 0; j < 4; j++) sacc[i][j] = 0.f;

        #pragma unroll
        for (int ks = 0; ks < 4; ks++) {
            unsigned qh[4], ql[4];
            unsigned qa = sb + qrow * ATS + ks * 32 + qcoloff;
            LDSM4(qh, qa);
            LDSM4(ql, qa + ATT_QL);
            #pragma unroll
            for (int gg = 0; gg < 4; gg++) {
                unsigned ka = kb + (gg * 16 + kro) * ATS + ks * 32 + kco;
                unsigned kh[4], kl[4];
                LDSM4(kh, ka);
                LDSM4(kl, ka + 9216);
                float* cA = sacc[2 * gg];
                float* cB = sacc[2 * gg + 1];
                mma_bf16(cA[0], cA[1], cA[2], cA[3], qh[0], qh[1], qh[2], qh[3], kh[0], kh[1]);
                mma_bf16(cA[0], cA[1], cA[2], cA[3], qh[0], qh[1], qh[2], qh[3], kl[0], kl[1]);
                mma_bf16(cA[0], cA[1], cA[2], cA[3], ql[0], ql[1], ql[2], ql[3], kh[0], kh[1]);
                mma_bf16(cB[0], cB[1], cB[2], cB[3], qh[0], qh[1], qh[2], qh[3], kh[2], kh[3]);
                mma_bf16(cB[0], cB[1], cB[2], cB[3], qh[0], qh[1], qh[2], qh[3], kl[2], kl[3]);
                mma_bf16(cB[0], cB[1], cB[2], cB[3], ql[0], ql[1], ql[2], ql[3], kh[2], kh[3]);
            }
        }

        // ---- scale + mask + online softmax ----
        const int r0 = t0 + wid * 16 + (lane >> 2);
        const int* mp = mask + (size_t)b * CDIM * CDIM + (size_t)r0 * CDIM
                        + s * 64 + (lane & 3) * 2;
        float mx0 = -1e30f, mx1 = -1e30f;
        #pragma unroll
        for (int nt = 0; nt < 8; nt++) {
            int2 m0 = *(const int2*)(mp + nt * 8);
            int2 m1 = *(const int2*)(mp + 8 * CDIM + nt * 8);
            float v0 = sacc[nt][0] * 0.125f; if (m0.x == 0) v0 = -1e9f;
            float v1 = sacc[nt][1] * 0.125f; if (m0.y == 0) v1 = -1e9f;
            float v2 = sacc[nt][2] * 0.125f; if (m1.x == 0) v2 = -1e9f;
            float v3 = sacc[nt][3] * 0.125f; if (m1.y == 0) v3 = -1e9f;
            sacc[nt][0] = v0; sacc[nt][1] = v1; sacc[nt][2] = v2; sacc[nt][3] = v3;
            mx0 = fmaxf(mx0, fmaxf(v0, v1));
            mx1 = fmaxf(mx1, fmaxf(v2, v3));
        }
        mx0 = fmaxf(mx0, __shfl_xor_sync(0xFFFFFFFFu, mx0, 1));
        mx0 = fmaxf(mx0, __shfl_xor_sync(0xFFFFFFFFu, mx0, 2));
        mx1 = fmaxf(mx1, __shfl_xor_sync(0xFFFFFFFFu, mx1, 1));
        mx1 = fmaxf(mx1, __shfl_xor_sync(0xFFFFFFFFu, mx1, 2));

        float mn0 = fmaxf(mrun0, mx0), mn1 = fmaxf(mrun1, mx1);
        float f0 = __expf(mrun0 - mn0), f1 = __expf(mrun1 - mn1);
        mrun0 = mn0; mrun1 = mn1;

        float sum0 = 0.f, sum1 = 0.f;
        #pragma unroll
        for (int nt = 0; nt < 8; nt++) {
            float p0 = __expf(sacc[nt][0] - mn0);
            float p1 = __expf(sacc[nt][1] - mn0);
            float p2 = __expf(sacc[nt][2] - mn1);
            float p3 = __expf(sacc[nt][3] - mn1);
            sacc[nt][0] = p0; sacc[nt][1] = p1; sacc[nt][2] = p2; sacc[nt][3] = p3;
            sum0 += p0 + p1; sum1 += p2 + p3;
        }
        sum0 += __shfl_xor_sync(0xFFFFFFFFu, sum0, 1);
        sum0 += __shfl_xor_sync(0xFFFFFFFFu, sum0, 2);
        sum1 += __shfl_xor_sync(0xFFFFFFFFu, sum1, 1);
        sum1 += __shfl_xor_sync(0xFFFFFFFFu, sum1, 2);
        lrun0 = lrun0 * f0 + sum0;
        lrun1 = lrun1 * f1 + sum1;

        #pragma unroll
        for (int nt = 0; nt < 8; nt++) {
            oacc[nt][0] *= f0; oacc[nt][1] *= f0;
            oacc[nt][2] *= f1; oacc[nt][3] *= f1;
        }

        // ---- O += P V (P in regs as A-frag; split hi/lo) ----
        #pragma unroll
        for (int ks = 0; ks < 4; ks++) {
            unsigned ah[4], al[4];
            #pragma unroll
            for (int h2i = 0; h2i < 2; h2i++) {
                float x0 = sacc[2 * ks + h2i][0], x1 = sacc[2 * ks + h2i][1];
                float x2 = sacc[2 * ks + h2i][2], x3 = sacc[2 * ks + h2i][3];
                __nv_bfloat162 hA = __floats2bfloat162_rn(x0, x1);
                __nv_bfloat162 hB = __floats2bfloat162_rn(x2, x3);
                ah[0 + 2 * h2i] = *(unsigned*)&hA;
                ah[1 + 2 * h2i] = *(unsigned*)&hB;
                __nv_bfloat162 lA = __floats2bfloat162_rn(x0 - __low2float(hA),
                                                          x1 - __high2float(hA));
                __nv_bfloat162 lB = __floats2bfloat162_rn(x2 - __low2float(hB),
                                                          x3 - __high2float(hB));
                al[0 + 2 * h2i] = *(unsigned*)&lA;
                al[1 + 2 * h2i] = *(unsigned*)&lB;
            }
            // reorder: a-frag = {rowlo_klo, rowhi_klo, rowlo_khi, rowhi_khi}
            unsigned a0 = ah[0], a1 = ah[1], a2 = ah[2], a3 = ah[3];
            unsigned b0 = al[0], b1 = al[1], b2 = al[2], b3 = al[3];
            #pragma unroll
            for (int gg = 0; gg < 4; gg++) {
                unsigned va = kb + 2 * 9216 + (ks * 16 + vro) * ATS + gg * 32 + vco;
                unsigned vh[4], vl[4];
                LDSM4T(vh, va);
                LDSM4T(vl, va + 9216);
                float* cA = oacc[2 * gg];
                float* cB = oacc[2 * gg + 1];
                mma_bf16(cA[0], cA[1], cA[2], cA[3], a0, a1, a2, a3, vh[0], vh[1]);
                mma_bf16(cA[0], cA[1], cA[2], cA[3], a0, a1, a2, a3, vl[0], vl[1]);
                mma_bf16(cA[0], cA[1], cA[2], cA[3], b0, b1, b2, b3, vh[0], vh[1]);
                mma_bf16(cB[0], cB[1], cB[2], cB[3], a0, a1, a2, a3, vh[2], vh[3]);
                mma_bf16(cB[0], cB[1], cB[2], cB[3], a0, a1, a2, a3, vl[2], vl[3]);
                mma_bf16(cB[0], cB[1], cB[2], cB[3], b0, b1, b2, b3, vh[2], vh[3]);
            }
        }
    }

    // ---- epilogue: normalize, split to bf16 hi/lo, store ----
    float li0 = 1.f / lrun0, li1 = 1.f / lrun1;
    const int r0g = t0 + wid * 16 + (lane >> 2);
    const size_t ob = (size_t)b * CDIM * CDIM + hb;
    #pragma unroll
    for (int nt = 0; nt < 8; nt++) {
        int col = nt * 8 + (lane & 3) * 2;
        float v0 = oacc[nt][0] * li0, v1 = oacc[nt][1] * li0;
        __nv_bfloat162 h2 = __floats2bfloat162_rn(v0, v1);
        __nv_bfloat162 l2 = __floats2bfloat162_rn(v0 - __low2float(h2),
                                                  v1 - __high2float(h2));
        *(__nv_bfloat162*)(g_AOh + ob + (size_t)r0g * CDIM + col) = h2;
        *(__nv_bfloat162*)(g_AOl + ob + (size_t)r0g * CDIM + col) = l2;
        float v2 = oacc[nt][2] * li1, v3 = oacc[nt][3] * li1;
        __nv_bfloat162 h3 = __floats2bfloat162_rn(v2, v3);
        __nv_bfloat162 l3 = __floats2bfloat162_rn(v2 - __low2float(h3),
                                                  v3 - __high2float(h3));
        *(__nv_bfloat162*)(g_AOh + ob + (size_t)(r0g + 8) * CDIM + col) = h3;
        *(__nv_bfloat162*)(g_AOl + ob + (size_t)(r0g + 8) * CDIM + col) = l3;
    }
}

// ============================================================================
extern "C" void kernel_launch(void* const* d_in, const int* in_sizes, int n_in,
                              void* d_out, int out_size)
{
    const float* q    = (const float*)d_in[0];
    const float* k    = (const float*)d_in[1];
    const float* v    = (const float*)d_in[2];
    const float* Wq   = (const float*)d_in[3];
    const float* bq   = (const float*)d_in[4];
    const float* Wk   = (const float*)d_in[5];
    const float* bk   = (const float*)d_in[6];
    const float* Wv   = (const float*)d_in[7];
    const float* bv   = (const float*)d_in[8];
    const float* Wo   = (const float*)d_in[9];
    const float* bo   = (const float*)d_in[10];
    const int*   mask = (const int*)d_in[11];

    // 1) split weights (conv + Wo)
    wsplit_kernel<<<dim3(1024, 4), 256>>>(Wq, Wk, Wv, Wo);

    // 2) im2col with bf16 split
    im2col_kernel<<<dim3(8, 32, 24), 256>>>(q, k, v);

    // 3) conv GEMM (bf16-split mma), epilogue emits Q/K/V hi/lo
    const int gemm_smem = 2 * BUFB;
    cudaFuncSetAttribute(conv_mma_kernel,
                         cudaFuncAttributeMaxDynamicSharedMemorySize, gemm_smem);
    conv_mma_kernel<<<dim3(8, 8, 24), 256, gemm_smem>>>(bq, bk, bv);

    // 4) attention (mma + online softmax)
    cudaFuncSetAttribute(attn_mma_kernel,
                         cudaFuncAttributeMaxDynamicSharedMemorySize, ATT_SMEM);
    attn_mma_kernel<<<dim3(8, 128), 256, ATT_SMEM>>>(mask);

    // 5) projection GEMM
    cudaFuncSetAttribute(proj_mma_kernel,
                         cudaFuncAttributeMaxDynamicSharedMemorySize, gemm_smem);
    proj_mma_kernel<<<dim3(8, 8, 8), 256, gemm_smem>>>(bo, (float*)d_out);
}